// round 1
// baseline (speedup 1.0000x reference)
#include <cuda_runtime.h>
#include <cstddef>

#define LSEQ 2048
#define DM   1024
#define DIN  2048
#define NST  16
#define DTR  64
#define XD   96     // DTR + 2*NST
#define KCONV 4

// ---------------- scratch (device globals; no allocation allowed) ----------------
__device__ float g_xr[(size_t)LSEQ * 2 * DIN];            // 32 MB : [xi_raw | res]
__device__ float g_xi[(size_t)LSEQ * DIN];                // 16 MB : conv+swish output (u)
__device__ float g_xdbl[(size_t)LSEQ * XD];               // delta_r | B | C
__device__ float g_delta[(size_t)LSEQ * DIN];             // 16 MB
__device__ float g_w[(size_t)LSEQ * DIN * NST];           // 256 MB : exp(suffix-sum dA)
__device__ float g_y[(size_t)LSEQ * DIN];                 // 16 MB : gated scan output
__device__ float g_part[(size_t)16 * LSEQ * XD];          // split-K partials for GEMM2

// ---------------- helpers ----------------
__device__ __forceinline__ float fast_exp(float x) {
    // e^x = 2^(x*log2e). ex2.approx: ~2^-22 rel err, correct underflow-to-zero,
    // independent of -use_fast_math settings.
    float y;
    asm("ex2.approx.f32 %0, %1;" : "=f"(y) : "f"(x * 1.4426950408889634f));
    return y;
}

__device__ __forceinline__ float swish_f(float v) {
    return v / (1.0f + fast_exp(-v));
}

__device__ __forceinline__ float softplus_f(float v) {
    // log1p(exp(-|v|)) + max(v,0)  (same stable form as jax.nn.softplus)
    return log1pf(fast_exp(-fabsf(v))) + fmaxf(v, 0.0f);
}

// ---------------- generic fp32 SIMT GEMM: C[M,N] = A[M,K]@B[K,N] (+bias,+act) ----
// 128x128 tile, BK=16, 256 threads, 8x8 per thread.
// gridDim.z > 1 => split-K: block z handles K-chunk z, writes raw partial to
// C + z*M*N (no epilogue). mode: 0=none, 1=+bias, 2=+bias then softplus.
#define BM 128
#define BN 128
#define BK 16

__global__ void gemm_kernel(const float* __restrict__ A, const float* __restrict__ B,
                            const float* __restrict__ bias, float* __restrict__ C,
                            int M, int N, int K, int lda, int mode)
{
    __shared__ __align__(16) float As[BK][BM];
    __shared__ __align__(16) float Bs[BK][BN];

    const int tid = threadIdx.x;
    const int tx = tid & 15;          // 0..15 -> N
    const int ty = tid >> 4;          // 0..15 -> M
    const int m0 = blockIdx.y * BM;
    const int n0 = blockIdx.x * BN;

    const int splits = gridDim.z;
    const int Kc = K / splits;
    const int kbeg = blockIdx.z * Kc;
    const int kend = kbeg + Kc;

    float acc[8][8];
#pragma unroll
    for (int i = 0; i < 8; i++)
#pragma unroll
        for (int j = 0; j < 8; j++) acc[i][j] = 0.0f;

    for (int k0 = kbeg; k0 < kend; k0 += BK) {
        // load A tile 128x16 (transposed into As[k][m]); 512 float4 / 256 thr
#pragma unroll
        for (int i = 0; i < 2; i++) {
            int lin = tid + i * 256;
            int r = lin >> 2;
            int kk = (lin & 3) * 4;
            float4 v = *(const float4*)(A + (size_t)(m0 + r) * lda + (k0 + kk));
            As[kk + 0][r] = v.x; As[kk + 1][r] = v.y;
            As[kk + 2][r] = v.z; As[kk + 3][r] = v.w;
        }
        // load B tile 16x128
#pragma unroll
        for (int i = 0; i < 2; i++) {
            int lin = tid + i * 256;
            int r = lin >> 5;
            int c = (lin & 31) * 4;
            int gn = n0 + c;
            float4 v = make_float4(0.f, 0.f, 0.f, 0.f);
            if (gn < N) v = *(const float4*)(B + (size_t)(k0 + r) * N + gn);
            *(float4*)&Bs[r][c] = v;
        }
        __syncthreads();

#pragma unroll
        for (int k = 0; k < BK; k++) {
            float ra[8], rb[8];
            *(float4*)&ra[0] = *(const float4*)&As[k][ty * 8];
            *(float4*)&ra[4] = *(const float4*)&As[k][ty * 8 + 4];
            *(float4*)&rb[0] = *(const float4*)&Bs[k][tx * 8];
            *(float4*)&rb[4] = *(const float4*)&Bs[k][tx * 8 + 4];
#pragma unroll
            for (int i = 0; i < 8; i++)
#pragma unroll
                for (int j = 0; j < 8; j++)
                    acc[i][j] = fmaf(ra[i], rb[j], acc[i][j]);
        }
        __syncthreads();
    }

    float* Cout = C;
    if (splits > 1) Cout += (size_t)blockIdx.z * M * N;

#pragma unroll
    for (int i = 0; i < 8; i++) {
        int gm = m0 + ty * 8 + i;
        if (gm >= M) continue;
#pragma unroll
        for (int j = 0; j < 8; j++) {
            int gn = n0 + tx * 8 + j;
            if (gn >= N) continue;
            float v = acc[i][j];
            if (splits == 1) {
                if (mode >= 1 && bias) v += bias[gn];
                if (mode == 2) v = softplus_f(v);
            }
            Cout[(size_t)gm * N + gn] = v;
        }
    }
}

__global__ void reduce_split_kernel(const float* __restrict__ part, float* __restrict__ out,
                                    int total, int splits)
{
    int i = blockIdx.x * blockDim.x + threadIdx.x;
    if (i >= total) return;
    float s = 0.0f;
    for (int z = 0; z < splits; z++) s += part[(size_t)z * total + i];
    out[i] = s;
}

// ---------------- depthwise causal conv (K=4) + bias + swish ----------------
__global__ void conv_swish_kernel(const float* __restrict__ xr,
                                  const float* __restrict__ cw,
                                  const float* __restrict__ cb,
                                  float* __restrict__ xi)
{
    int idx = blockIdx.x * blockDim.x + threadIdx.x;
    if (idx >= LSEQ * DIN) return;
    int t = idx >> 11;           // /DIN
    int d = idx & (DIN - 1);
    float acc = cb[d];
#pragma unroll
    for (int k = 0; k < KCONV; k++) {
        int tt = t - (KCONV - 1) + k;
        if (tt >= 0) acc = fmaf(cw[d * KCONV + k], xr[(size_t)tt * (2 * DIN) + d], acc);
    }
    xi[idx] = swish_f(acc);
}

// ---------------- scan backward: w[t] = exp(sum_{s>t} delta_s * A) ----------------
// thread g = d*16+n. Accumulation order matches flip->cumsum->flip (adds from the
// tail), so the "live" region near the end has small partial sums (benign rounding).
__global__ void scan_backward_kernel(const float* __restrict__ delta,
                                     const float* __restrict__ A_log,
                                     float* __restrict__ wbuf)
{
    int g = blockIdx.x * blockDim.x + threadIdx.x;   // 0..32767
    int d = g >> 4;
    float Aval = -fast_exp(A_log[g]);                // A = -exp(A_log)
    float S = 0.0f;
    for (int t = LSEQ - 1; t >= 0; t--) {
        wbuf[(size_t)t * (DIN * NST) + g] = fast_exp(S);
        S = fmaf(delta[(size_t)t * DIN + d], Aval, S);
    }
}

// ---------------- scan forward: cumsum, divide, C-proj, +u*D, gate with swish(res)
__global__ void scan_forward_kernel(const float* __restrict__ delta,
                                    const float* __restrict__ u,
                                    const float* __restrict__ xdbl,
                                    const float* __restrict__ xr,
                                    const float* __restrict__ wbuf,
                                    const float* __restrict__ Dv,
                                    float* __restrict__ y)
{
    int g = blockIdx.x * blockDim.x + threadIdx.x;   // 0..32767
    int d = g >> 4;
    int n = g & 15;
    float Dd = Dv[d];
    float c = 0.0f;
    for (int t = 0; t < LSEQ; t++) {
        float w  = wbuf[(size_t)t * (DIN * NST) + g];
        float de = delta[(size_t)t * DIN + d];
        float uu = u[(size_t)t * DIN + d];
        float Bn = xdbl[(size_t)t * XD + DTR + n];
        float Cn = xdbl[(size_t)t * XD + DTR + NST + n];
        float dbu = de * uu * Bn;
        c = fmaf(dbu, w, c);
        float xs = c / (w + 1e-12f);
        float v = xs * Cn;
        // reduce over the 16 state lanes
        v += __shfl_down_sync(0xffffffffu, v, 8, 16);
        v += __shfl_down_sync(0xffffffffu, v, 4, 16);
        v += __shfl_down_sync(0xffffffffu, v, 2, 16);
        v += __shfl_down_sync(0xffffffffu, v, 1, 16);
        if (n == 0) {
            float res = xr[(size_t)t * (2 * DIN) + DIN + d];
            y[(size_t)t * DIN + d] = (v + uu * Dd) * swish_f(res);
        }
    }
}

// ---------------- launch ----------------
extern "C" void kernel_launch(void* const* d_in, const int* in_sizes, int n_in,
                              void* d_out, int out_size)
{
    const float* x      = (const float*)d_in[0];
    const float* W_in   = (const float*)d_in[1];
    const float* conv_w = (const float*)d_in[2];
    const float* conv_b = (const float*)d_in[3];
    const float* W_x    = (const float*)d_in[4];
    const float* W_dt   = (const float*)d_in[5];
    const float* b_dt   = (const float*)d_in[6];
    const float* A_log  = (const float*)d_in[7];
    const float* Dv     = (const float*)d_in[8];
    const float* W_out  = (const float*)d_in[9];
    const float* b_out  = (const float*)d_in[10];
    float* out = (float*)d_out;
    (void)in_sizes; (void)n_in; (void)out_size;

    float *xr, *xi, *xdbl, *delta, *wbuf, *y, *part;
    cudaGetSymbolAddress((void**)&xr,    g_xr);
    cudaGetSymbolAddress((void**)&xi,    g_xi);
    cudaGetSymbolAddress((void**)&xdbl,  g_xdbl);
    cudaGetSymbolAddress((void**)&delta, g_delta);
    cudaGetSymbolAddress((void**)&wbuf,  g_w);
    cudaGetSymbolAddress((void**)&y,     g_y);
    cudaGetSymbolAddress((void**)&part,  g_part);

    dim3 blk(256);

    // 1) x_and_res = x @ W_in                     (2048 x 4096 x 1024)
    gemm_kernel<<<dim3((2 * DIN) / BN, LSEQ / BM, 1), blk>>>(
        x, W_in, nullptr, xr, LSEQ, 2 * DIN, DM, DM, 0);

    // 2) xi = swish(causal depthwise conv(xi_raw) + conv_b)
    conv_swish_kernel<<<(LSEQ * DIN + 255) / 256, blk>>>(xr, conv_w, conv_b, xi);

    // 3) x_dbl = xi @ W_x                         (2048 x 96 x 2048), split-K=16
    gemm_kernel<<<dim3(1, LSEQ / BM, 16), blk>>>(
        xi, W_x, nullptr, part, LSEQ, XD, DIN, DIN, 0);
    reduce_split_kernel<<<(LSEQ * XD + 255) / 256, blk>>>(part, xdbl, LSEQ * XD, 16);

    // 4) delta = softplus(delta_r @ W_dt + b_dt)  (2048 x 2048 x 64), lda=96
    gemm_kernel<<<dim3(DIN / BN, LSEQ / BM, 1), blk>>>(
        xdbl, W_dt, b_dt, delta, LSEQ, DIN, DTR, XD, 2);

    // 5) selective scan (reference-faithful exp/cumsum trick)
    scan_backward_kernel<<<(DIN * NST) / 256, blk>>>(delta, A_log, wbuf);
    scan_forward_kernel<<<(DIN * NST) / 256, blk>>>(delta, xi, xdbl, xr, wbuf, Dv, y);

    // 6) out = y_gated @ W_out + b_out            (2048 x 1024 x 2048)
    gemm_kernel<<<dim3(DM / BN, LSEQ / BM, 1), blk>>>(
        y, W_out, b_out, out, LSEQ, DM, DIN, DIN, 1);
}

// round 2
// speedup vs baseline: 3.5837x; 3.5837x over previous
#include <cuda_runtime.h>
#include <cstddef>

#define LSEQ 2048
#define DM   1024
#define DIN  2048
#define NST  16
#define DTR  64
#define XD   96     // DTR + 2*NST
#define KCONV 4

// ---------------- scratch (device globals; no allocation allowed) ----------------
__device__ float g_xr[(size_t)LSEQ * 2 * DIN];            // 32 MB : [xi_raw | res]
__device__ float g_xi[(size_t)LSEQ * DIN];                // 16 MB : conv+swish output (u)
__device__ float g_xdbl[(size_t)LSEQ * XD];               // delta_r | B | C
__device__ float g_delta[(size_t)LSEQ * DIN];             // 16 MB
__device__ float g_R[(size_t)DIN * LSEQ];                 // 16 MB : suffix sums of delta, [d][t]
__device__ float g_yacc[(size_t)LSEQ * DIN];              // 16 MB : scan C-projection accumulator
__device__ float g_y[(size_t)LSEQ * DIN];                 // 16 MB : gated scan output
__device__ float g_part[(size_t)16 * LSEQ * XD];          // split-K partials for GEMM2

// ---------------- helpers ----------------
__device__ __forceinline__ float fast_exp(float x) {
    float y;
    asm("ex2.approx.f32 %0, %1;" : "=f"(y) : "f"(x * 1.4426950408889634f));
    return y;
}
__device__ __forceinline__ float fast_rcp(float x) {
    float y;
    asm("rcp.approx.f32 %0, %1;" : "=f"(y) : "f"(x));
    return y;
}
__device__ __forceinline__ float swish_f(float v) {
    return v / (1.0f + fast_exp(-v));
}
__device__ __forceinline__ float softplus_f(float v) {
    return log1pf(fast_exp(-fabsf(v))) + fmaxf(v, 0.0f);
}

// ---------------- generic fp32 SIMT GEMM: C[M,N] = A[M,K]@B[K,N] (+bias,+act) ----
#define BM 128
#define BN 128
#define BK 16

__global__ void __launch_bounds__(256)
gemm_kernel(const float* __restrict__ A, const float* __restrict__ B,
            const float* __restrict__ bias, float* __restrict__ C,
            int M, int N, int K, int lda, int mode)
{
    __shared__ __align__(16) float As[BK][BM];
    __shared__ __align__(16) float Bs[BK][BN];

    const int tid = threadIdx.x;
    const int tx = tid & 15;
    const int ty = tid >> 4;
    const int m0 = blockIdx.y * BM;
    const int n0 = blockIdx.x * BN;

    const int splits = gridDim.z;
    const int Kc = K / splits;
    const int kbeg = blockIdx.z * Kc;
    const int kend = kbeg + Kc;

    float acc[8][8];
#pragma unroll
    for (int i = 0; i < 8; i++)
#pragma unroll
        for (int j = 0; j < 8; j++) acc[i][j] = 0.0f;

    for (int k0 = kbeg; k0 < kend; k0 += BK) {
#pragma unroll
        for (int i = 0; i < 2; i++) {
            int lin = tid + i * 256;
            int r = lin >> 2;
            int kk = (lin & 3) * 4;
            float4 v = *(const float4*)(A + (size_t)(m0 + r) * lda + (k0 + kk));
            As[kk + 0][r] = v.x; As[kk + 1][r] = v.y;
            As[kk + 2][r] = v.z; As[kk + 3][r] = v.w;
        }
#pragma unroll
        for (int i = 0; i < 2; i++) {
            int lin = tid + i * 256;
            int r = lin >> 5;
            int c = (lin & 31) * 4;
            int gn = n0 + c;
            float4 v = make_float4(0.f, 0.f, 0.f, 0.f);
            if (gn < N) v = *(const float4*)(B + (size_t)(k0 + r) * N + gn);
            *(float4*)&Bs[r][c] = v;
        }
        __syncthreads();

#pragma unroll
        for (int k = 0; k < BK; k++) {
            float ra[8], rb[8];
            *(float4*)&ra[0] = *(const float4*)&As[k][ty * 8];
            *(float4*)&ra[4] = *(const float4*)&As[k][ty * 8 + 4];
            *(float4*)&rb[0] = *(const float4*)&Bs[k][tx * 8];
            *(float4*)&rb[4] = *(const float4*)&Bs[k][tx * 8 + 4];
#pragma unroll
            for (int i = 0; i < 8; i++)
#pragma unroll
                for (int j = 0; j < 8; j++)
                    acc[i][j] = fmaf(ra[i], rb[j], acc[i][j]);
        }
        __syncthreads();
    }

    float* Cout = C;
    if (splits > 1) Cout += (size_t)blockIdx.z * M * N;

#pragma unroll
    for (int i = 0; i < 8; i++) {
        int gm = m0 + ty * 8 + i;
        if (gm >= M) continue;
#pragma unroll
        for (int j = 0; j < 8; j++) {
            int gn = n0 + tx * 8 + j;
            if (gn >= N) continue;
            float v = acc[i][j];
            if (splits == 1) {
                if (mode >= 1 && bias) v += bias[gn];
                if (mode == 2) v = softplus_f(v);
            }
            Cout[(size_t)gm * N + gn] = v;
        }
    }
}

__global__ void reduce_split_kernel(const float* __restrict__ part, float* __restrict__ out,
                                    int total, int splits)
{
    int i = blockIdx.x * blockDim.x + threadIdx.x;
    if (i >= total) return;
    float s = 0.0f;
    for (int z = 0; z < splits; z++) s += part[(size_t)z * total + i];
    out[i] = s;
}

// ---------------- depthwise causal conv (K=4) + bias + swish ----------------
__global__ void conv_swish_kernel(const float* __restrict__ xr,
                                  const float* __restrict__ cw,
                                  const float* __restrict__ cb,
                                  float* __restrict__ xi)
{
    int idx = blockIdx.x * blockDim.x + threadIdx.x;
    if (idx >= LSEQ * DIN) return;
    int t = idx >> 11;
    int d = idx & (DIN - 1);
    float acc = cb[d];
#pragma unroll
    for (int k = 0; k < KCONV; k++) {
        int tt = t - (KCONV - 1) + k;
        if (tt >= 0) acc = fmaf(cw[d * KCONV + k], xr[(size_t)tt * (2 * DIN) + d], acc);
    }
    xi[idx] = swish_f(acc);
}

// ---------------- suffix scan: R[d][t] = sum_{s>t} delta[s][d] ----------------
// one block (256 threads) per channel d; walk the 8 chunks of 256 from the tail.
__global__ void suffix_scan_kernel(const float* __restrict__ delta, float* __restrict__ R)
{
    __shared__ float sh[256];
    const int d = blockIdx.x;
    const int tid = threadIdx.x;
    const int r = 255 - tid;              // reversed index: prefix over r == suffix over t
    float carry = 0.0f;
    for (int c = LSEQ / 256 - 1; c >= 0; c--) {
        int t = c * 256 + tid;
        float v = delta[(size_t)t * DIN + d];
        sh[r] = v;
        __syncthreads();
        float val = v;
#pragma unroll
        for (int off = 1; off < 256; off <<= 1) {
            float add = (r >= off) ? sh[r - off] : 0.0f;
            __syncthreads();
            val += add;
            sh[r] = val;
            __syncthreads();
        }
        // val = inclusive suffix within chunk; exclusive = val - v
        R[(size_t)d * LSEQ + t] = (val - v) + carry;
        float chunk_total = sh[255];
        __syncthreads();
        carry += chunk_total;
    }
}

__global__ void zero_kernel(float* __restrict__ p, int total)
{
    int i = blockIdx.x * blockDim.x + threadIdx.x;
    if (i < total) p[i] = 0.0f;
}

// ---------------- sparse scan forward ----------------
// Reference: w[t,d,n] = exp(A[d,n] * R[t,d]);  c = cumsum_t(delta*u*B*w);
// xs = c/(w+1e-12); y += xs*C.  w underflows to exactly 0 outside a short live
// tail (and c stays 0 there, so xs=0, matching the reference bit-for-bit in
// effect). We binary-search the live start on the monotone-decreasing R and
// only walk the tail.
__global__ void scan_sparse_kernel(const float* __restrict__ delta,
                                   const float* __restrict__ u,
                                   const float* __restrict__ xdbl,
                                   const float* __restrict__ A_log,
                                   const float* __restrict__ R,
                                   float* __restrict__ yacc)
{
    int g = blockIdx.x * blockDim.x + threadIdx.x;   // 0..32767
    int d = g >> 4;
    int n = g & 15;
    float An = -fast_exp(A_log[g]);                  // A = -exp(A_log), layout (DIN, NST)
    const float* Rd = R + (size_t)d * LSEQ;

    // first t with An*Rd[t] > -90  <=>  Rd[t] < 90/(-An).  Rd is non-increasing.
    float thresh = 90.0f / (-An);
    int lo = 0, hi = LSEQ;
    while (lo < hi) {
        int mid = (lo + hi) >> 1;
        if (Rd[mid] < thresh) hi = mid; else lo = mid + 1;
    }

    float c = 0.0f;
    for (int t = lo; t < LSEQ; t++) {
        float w  = fast_exp(An * Rd[t]);
        float de = delta[(size_t)t * DIN + d];
        float uu = u[(size_t)t * DIN + d];
        float Bn = xdbl[(size_t)t * XD + DTR + n];
        float Cn = xdbl[(size_t)t * XD + DTR + NST + n];
        c = fmaf(de * uu * Bn, w, c);
        float xs = c * fast_rcp(w + 1e-12f);
        atomicAdd(&yacc[(size_t)t * DIN + d], xs * Cn);
    }
}

// ---------------- finalize: y = (yacc + u*D) * swish(res) ----------------
__global__ void finalize_y_kernel(const float* __restrict__ yacc,
                                  const float* __restrict__ u,
                                  const float* __restrict__ xr,
                                  const float* __restrict__ Dv,
                                  float* __restrict__ y)
{
    int idx = blockIdx.x * blockDim.x + threadIdx.x;
    if (idx >= LSEQ * DIN) return;
    int t = idx >> 11;
    int d = idx & (DIN - 1);
    float res = xr[(size_t)t * (2 * DIN) + DIN + d];
    y[idx] = (yacc[idx] + u[idx] * Dv[d]) * swish_f(res);
}

// ---------------- launch ----------------
extern "C" void kernel_launch(void* const* d_in, const int* in_sizes, int n_in,
                              void* d_out, int out_size)
{
    const float* x      = (const float*)d_in[0];
    const float* W_in   = (const float*)d_in[1];
    const float* conv_w = (const float*)d_in[2];
    const float* conv_b = (const float*)d_in[3];
    const float* W_x    = (const float*)d_in[4];
    const float* W_dt   = (const float*)d_in[5];
    const float* b_dt   = (const float*)d_in[6];
    const float* A_log  = (const float*)d_in[7];
    const float* Dv     = (const float*)d_in[8];
    const float* W_out  = (const float*)d_in[9];
    const float* b_out  = (const float*)d_in[10];
    float* out = (float*)d_out;
    (void)in_sizes; (void)n_in; (void)out_size;

    float *xr, *xi, *xdbl, *delta, *Rbuf, *yacc, *y, *part;
    cudaGetSymbolAddress((void**)&xr,    g_xr);
    cudaGetSymbolAddress((void**)&xi,    g_xi);
    cudaGetSymbolAddress((void**)&xdbl,  g_xdbl);
    cudaGetSymbolAddress((void**)&delta, g_delta);
    cudaGetSymbolAddress((void**)&Rbuf,  g_R);
    cudaGetSymbolAddress((void**)&yacc,  g_yacc);
    cudaGetSymbolAddress((void**)&y,     g_y);
    cudaGetSymbolAddress((void**)&part,  g_part);

    dim3 blk(256);

    // 1) x_and_res = x @ W_in                     (2048 x 4096 x 1024)
    gemm_kernel<<<dim3((2 * DIN) / BN, LSEQ / BM, 1), blk>>>(
        x, W_in, nullptr, xr, LSEQ, 2 * DIN, DM, DM, 0);

    // 2) xi = swish(causal depthwise conv(xi_raw) + conv_b)
    conv_swish_kernel<<<(LSEQ * DIN + 255) / 256, blk>>>(xr, conv_w, conv_b, xi);

    // 3) x_dbl = xi @ W_x                         (2048 x 96 x 2048), split-K=16
    gemm_kernel<<<dim3(1, LSEQ / BM, 16), blk>>>(
        xi, W_x, nullptr, part, LSEQ, XD, DIN, DIN, 0);
    reduce_split_kernel<<<(LSEQ * XD + 255) / 256, blk>>>(part, xdbl, LSEQ * XD, 16);

    // 4) delta = softplus(delta_r @ W_dt + b_dt)  (2048 x 2048 x 64), lda=96
    gemm_kernel<<<dim3(DIN / BN, LSEQ / BM, 1), blk>>>(
        xdbl, W_dt, b_dt, delta, LSEQ, DIN, DTR, XD, 2);

    // 5) selective scan: suffix sums + sparse live-tail walk
    zero_kernel<<<(LSEQ * DIN + 255) / 256, blk>>>(yacc, LSEQ * DIN);
    suffix_scan_kernel<<<DIN, blk>>>(delta, Rbuf);
    scan_sparse_kernel<<<(DIN * NST) / 256, blk>>>(delta, xi, xdbl, A_log, Rbuf, yacc);
    finalize_y_kernel<<<(LSEQ * DIN + 255) / 256, blk>>>(yacc, xi, xr, Dv, y);

    // 6) out = y_gated @ W_out + b_out            (2048 x 1024 x 2048)
    gemm_kernel<<<dim3(DM / BN, LSEQ / BM, 1), blk>>>(
        y, W_out, b_out, out, LSEQ, DM, DIN, DIN, 1);
}

// round 3
// speedup vs baseline: 6.1345x; 1.7118x over previous
#include <cuda_runtime.h>
#include <cstddef>
#include <cstdint>

#define LSEQ 2048
#define DM   1024
#define DIN  2048
#define NST  16
#define DTR  64
#define XD   96     // DTR + 2*NST
#define KCONV 4

// ---------------- scratch (device globals; no allocation allowed) ----------------
__device__ float g_xr[(size_t)LSEQ * 2 * DIN];            // [xi_raw | res]
__device__ float g_xi[(size_t)LSEQ * DIN];                // conv+swish output (u)
__device__ float g_xdbl[(size_t)LSEQ * XD];               // delta_r | B | C
__device__ float g_delta[(size_t)LSEQ * DIN];
__device__ float g_R[(size_t)DIN * LSEQ];                 // suffix sums of delta, [d][t]
__device__ float g_yacc[(size_t)LSEQ * DIN];
__device__ float g_y[(size_t)LSEQ * DIN];
__device__ float g_part[(size_t)16 * LSEQ * XD];          // split-K partials for GEMM2

// ---------------- helpers ----------------
__device__ __forceinline__ float fast_exp(float x) {
    float y;
    asm("ex2.approx.f32 %0, %1;" : "=f"(y) : "f"(x * 1.4426950408889634f));
    return y;
}
__device__ __forceinline__ float fast_rcp(float x) {
    float y;
    asm("rcp.approx.f32 %0, %1;" : "=f"(y) : "f"(x));
    return y;
}
__device__ __forceinline__ float swish_f(float v) {
    return v / (1.0f + fast_exp(-v));
}
__device__ __forceinline__ float softplus_f(float v) {
    return log1pf(fast_exp(-fabsf(v))) + fmaxf(v, 0.0f);
}
__device__ __forceinline__ float tf32_rna(float x) {
    uint32_t u;
    asm("cvt.rna.tf32.f32 %0, %1;" : "=r"(u) : "f"(x));
    return __uint_as_float(u);
}
__device__ __forceinline__ void mma8(float* d, const uint32_t* a, const uint32_t* b) {
    asm volatile("mma.sync.aligned.m16n8k8.row.col.f32.tf32.tf32.f32 "
        "{%0,%1,%2,%3}, {%4,%5,%6,%7}, {%8,%9}, {%0,%1,%2,%3};"
        : "+f"(d[0]), "+f"(d[1]), "+f"(d[2]), "+f"(d[3])
        : "r"(a[0]), "r"(a[1]), "r"(a[2]), "r"(a[3]), "r"(b[0]), "r"(b[1]));
}

// =============== TF32 tensor-core GEMM: C[M,N] = A[M,K]@B[K,N] (+bias) =========
// 128x128x32 tile, 256 threads (8 warps as 2x4 over 64x32 warp tiles).
// THREE=true: 3xTF32 (hi/lo split, ~fp32 accuracy). lda==K, ldb==N assumed.
// Double-buffered smem with register prefetch of the next K-tile.
template<bool THREE, int MODE>
__global__ void __launch_bounds__(256)
gemm_tf32_kernel(const float* __restrict__ A, const float* __restrict__ B,
                 const float* __restrict__ bias, float* __restrict__ C,
                 int M, int N, int K)
{
    extern __shared__ float sm[];
    constexpr int ASZ = 128 * 36;       // A tile floats (stride 36: pad, 16B-aligned, conflict-free)
    constexpr int BSZ = 32 * 132;       // B tile floats (stride 132)
    constexpr int STAGE = THREE ? 2 * (ASZ + BSZ) : (ASZ + BSZ);

    const int tid  = threadIdx.x;
    const int wid  = tid >> 5;
    const int lane = tid & 31;
    const int g    = lane >> 2;         // groupID (0..7)
    const int tg   = lane & 3;          // thread-in-group (0..3)
    const int wm0  = (wid >> 2) << 6;   // warp m origin: 0 / 64
    const int wn0  = (wid & 3) << 5;    // warp n origin: 0..96
    const int m0   = blockIdx.y << 7;
    const int n0   = blockIdx.x << 7;

    float acc[4][4][4];
#pragma unroll
    for (int i = 0; i < 4; i++)
#pragma unroll
        for (int j = 0; j < 4; j++)
#pragma unroll
            for (int q = 0; q < 4; q++) acc[i][j][q] = 0.0f;

    float4 ra[4], rb[4];

    auto ldg_tile = [&](int k0) {
#pragma unroll
        for (int i = 0; i < 4; i++) {
            int lin = tid + (i << 8);
            ra[i] = *(const float4*)(A + (size_t)(m0 + (lin >> 3)) * K + k0 + ((lin & 7) << 2));
            rb[i] = *(const float4*)(B + (size_t)(k0 + (lin >> 5)) * N + n0 + ((lin & 31) << 2));
        }
    };

    auto sts_tile = [&](int s) {
        float* As_h = sm + s * STAGE;
        float* Bs_h = As_h + (THREE ? 2 * ASZ : ASZ);
#pragma unroll
        for (int i = 0; i < 4; i++) {
            int lin = tid + (i << 8);
            int arow = lin >> 3, acol = (lin & 7) << 2;
            float4 h;
            h.x = tf32_rna(ra[i].x); h.y = tf32_rna(ra[i].y);
            h.z = tf32_rna(ra[i].z); h.w = tf32_rna(ra[i].w);
            *(float4*)(As_h + arow * 36 + acol) = h;
            if (THREE) {
                float4 l;
                l.x = tf32_rna(ra[i].x - h.x); l.y = tf32_rna(ra[i].y - h.y);
                l.z = tf32_rna(ra[i].z - h.z); l.w = tf32_rna(ra[i].w - h.w);
                *(float4*)(As_h + ASZ + arow * 36 + acol) = l;
            }
            int brow = lin >> 5, bcol = (lin & 31) << 2;
            float4 bh;
            bh.x = tf32_rna(rb[i].x); bh.y = tf32_rna(rb[i].y);
            bh.z = tf32_rna(rb[i].z); bh.w = tf32_rna(rb[i].w);
            *(float4*)(Bs_h + brow * 132 + bcol) = bh;
            if (THREE) {
                float4 bl;
                bl.x = tf32_rna(rb[i].x - bh.x); bl.y = tf32_rna(rb[i].y - bh.y);
                bl.z = tf32_rna(rb[i].z - bh.z); bl.w = tf32_rna(rb[i].w - bh.w);
                *(float4*)(Bs_h + BSZ + brow * 132 + bcol) = bl;
            }
        }
    };

    auto compute = [&](int s) {
        const float* As_h = sm + s * STAGE;
        const float* As_l = As_h + ASZ;
        const float* Bs_h = As_h + (THREE ? 2 * ASZ : ASZ);
        const float* Bs_l = Bs_h + BSZ;
#pragma unroll
        for (int j = 0; j < 4; j++) {
            const int kk = j << 3;
            uint32_t ah[4][4], bh[4][2];
            uint32_t al[4][4], bl[4][2];
#pragma unroll
            for (int nf = 0; nf < 4; nf++) {
                int bn = wn0 + (nf << 3) + g;
                bh[nf][0] = __float_as_uint(Bs_h[(kk + tg) * 132 + bn]);
                bh[nf][1] = __float_as_uint(Bs_h[(kk + tg + 4) * 132 + bn]);
                if (THREE) {
                    bl[nf][0] = __float_as_uint(Bs_l[(kk + tg) * 132 + bn]);
                    bl[nf][1] = __float_as_uint(Bs_l[(kk + tg + 4) * 132 + bn]);
                }
            }
#pragma unroll
            for (int mf = 0; mf < 4; mf++) {
                int rm = (wm0 + (mf << 4) + g) * 36 + kk + tg;
                ah[mf][0] = __float_as_uint(As_h[rm]);
                ah[mf][1] = __float_as_uint(As_h[rm + 8 * 36]);
                ah[mf][2] = __float_as_uint(As_h[rm + 4]);
                ah[mf][3] = __float_as_uint(As_h[rm + 8 * 36 + 4]);
                if (THREE) {
                    al[mf][0] = __float_as_uint(As_l[rm]);
                    al[mf][1] = __float_as_uint(As_l[rm + 8 * 36]);
                    al[mf][2] = __float_as_uint(As_l[rm + 4]);
                    al[mf][3] = __float_as_uint(As_l[rm + 8 * 36 + 4]);
                }
            }
#pragma unroll
            for (int mf = 0; mf < 4; mf++)
#pragma unroll
                for (int nf = 0; nf < 4; nf++) {
                    mma8(acc[mf][nf], ah[mf], bh[nf]);
                    if (THREE) {
                        mma8(acc[mf][nf], ah[mf], bl[nf]);
                        mma8(acc[mf][nf], al[mf], bh[nf]);
                    }
                }
        }
    };

    const int nt = K >> 5;
    ldg_tile(0);
    sts_tile(0);
    __syncthreads();
    for (int t = 0; t < nt; t++) {
        if (t + 1 < nt) ldg_tile((t + 1) << 5);
        compute(t & 1);
        if (t + 1 < nt) {
            __syncthreads();
            sts_tile((t + 1) & 1);
            __syncthreads();
        }
    }

    // epilogue
#pragma unroll
    for (int mf = 0; mf < 4; mf++)
#pragma unroll
        for (int nf = 0; nf < 4; nf++) {
            int row = m0 + wm0 + (mf << 4) + g;
            int col = n0 + wn0 + (nf << 3) + (tg << 1);
            float b0 = 0.0f, b1 = 0.0f;
            if (MODE >= 1) { b0 = bias[col]; b1 = bias[col + 1]; }
            float2 v0 = make_float2(acc[mf][nf][0] + b0, acc[mf][nf][1] + b1);
            float2 v1 = make_float2(acc[mf][nf][2] + b0, acc[mf][nf][3] + b1);
            *(float2*)(C + (size_t)row * N + col) = v0;
            *(float2*)(C + (size_t)(row + 8) * N + col) = v1;
        }
}

// ---------------- fp32 SIMT GEMM (kept for the two small GEMMs) ----------------
#define BM 128
#define BN 128
#define BK 16

__global__ void __launch_bounds__(256)
gemm_kernel(const float* __restrict__ A, const float* __restrict__ B,
            const float* __restrict__ bias, float* __restrict__ C,
            int M, int N, int K, int lda, int mode)
{
    __shared__ __align__(16) float As[BK][BM];
    __shared__ __align__(16) float Bs[BK][BN];

    const int tid = threadIdx.x;
    const int tx = tid & 15;
    const int ty = tid >> 4;
    const int m0 = blockIdx.y * BM;
    const int n0 = blockIdx.x * BN;

    const int splits = gridDim.z;
    const int Kc = K / splits;
    const int kbeg = blockIdx.z * Kc;
    const int kend = kbeg + Kc;

    float acc[8][8];
#pragma unroll
    for (int i = 0; i < 8; i++)
#pragma unroll
        for (int j = 0; j < 8; j++) acc[i][j] = 0.0f;

    for (int k0 = kbeg; k0 < kend; k0 += BK) {
#pragma unroll
        for (int i = 0; i < 2; i++) {
            int lin = tid + i * 256;
            int r = lin >> 2;
            int kk = (lin & 3) * 4;
            float4 v = *(const float4*)(A + (size_t)(m0 + r) * lda + (k0 + kk));
            As[kk + 0][r] = v.x; As[kk + 1][r] = v.y;
            As[kk + 2][r] = v.z; As[kk + 3][r] = v.w;
        }
#pragma unroll
        for (int i = 0; i < 2; i++) {
            int lin = tid + i * 256;
            int r = lin >> 5;
            int c = (lin & 31) * 4;
            int gn = n0 + c;
            float4 v = make_float4(0.f, 0.f, 0.f, 0.f);
            if (gn < N) v = *(const float4*)(B + (size_t)(k0 + r) * N + gn);
            *(float4*)&Bs[r][c] = v;
        }
        __syncthreads();

#pragma unroll
        for (int k = 0; k < BK; k++) {
            float rva[8], rvb[8];
            *(float4*)&rva[0] = *(const float4*)&As[k][ty * 8];
            *(float4*)&rva[4] = *(const float4*)&As[k][ty * 8 + 4];
            *(float4*)&rvb[0] = *(const float4*)&Bs[k][tx * 8];
            *(float4*)&rvb[4] = *(const float4*)&Bs[k][tx * 8 + 4];
#pragma unroll
            for (int i = 0; i < 8; i++)
#pragma unroll
                for (int j = 0; j < 8; j++)
                    acc[i][j] = fmaf(rva[i], rvb[j], acc[i][j]);
        }
        __syncthreads();
    }

    float* Cout = C;
    if (splits > 1) Cout += (size_t)blockIdx.z * M * N;

#pragma unroll
    for (int i = 0; i < 8; i++) {
        int gm = m0 + ty * 8 + i;
        if (gm >= M) continue;
#pragma unroll
        for (int j = 0; j < 8; j++) {
            int gn = n0 + tx * 8 + j;
            if (gn >= N) continue;
            float v = acc[i][j];
            if (splits == 1) {
                if (mode >= 1 && bias) v += bias[gn];
                if (mode == 2) v = softplus_f(v);
            }
            Cout[(size_t)gm * N + gn] = v;
        }
    }
}

__global__ void reduce_split_kernel(const float* __restrict__ part, float* __restrict__ out,
                                    int total, int splits)
{
    int i = blockIdx.x * blockDim.x + threadIdx.x;
    if (i >= total) return;
    float s = 0.0f;
    for (int z = 0; z < splits; z++) s += part[(size_t)z * total + i];
    out[i] = s;
}

// ---------------- depthwise causal conv (K=4) + bias + swish ----------------
__global__ void conv_swish_kernel(const float* __restrict__ xr,
                                  const float* __restrict__ cw,
                                  const float* __restrict__ cb,
                                  float* __restrict__ xi)
{
    int idx = blockIdx.x * blockDim.x + threadIdx.x;
    if (idx >= LSEQ * DIN) return;
    int t = idx >> 11;
    int d = idx & (DIN - 1);
    float acc = cb[d];
#pragma unroll
    for (int k = 0; k < KCONV; k++) {
        int tt = t - (KCONV - 1) + k;
        if (tt >= 0) acc = fmaf(cw[d * KCONV + k], xr[(size_t)tt * (2 * DIN) + d], acc);
    }
    xi[idx] = swish_f(acc);
}

// ---------------- suffix scan: R[d][t] = sum_{s>t} delta[s][d] ----------------
__global__ void suffix_scan_kernel(const float* __restrict__ delta, float* __restrict__ R)
{
    __shared__ float sh[256];
    const int d = blockIdx.x;
    const int tid = threadIdx.x;
    const int r = 255 - tid;
    float carry = 0.0f;
    for (int c = LSEQ / 256 - 1; c >= 0; c--) {
        int t = c * 256 + tid;
        float v = delta[(size_t)t * DIN + d];
        sh[r] = v;
        __syncthreads();
        float val = v;
#pragma unroll
        for (int off = 1; off < 256; off <<= 1) {
            float add = (r >= off) ? sh[r - off] : 0.0f;
            __syncthreads();
            val += add;
            sh[r] = val;
            __syncthreads();
        }
        R[(size_t)d * LSEQ + t] = (val - v) + carry;
        float chunk_total = sh[255];
        __syncthreads();
        carry += chunk_total;
    }
}

__global__ void zero_kernel(float* __restrict__ p, int total)
{
    int i = blockIdx.x * blockDim.x + threadIdx.x;
    if (i < total) p[i] = 0.0f;
}

// ---------------- sparse scan forward (live-tail only; see R2 notes) ----------
__global__ void scan_sparse_kernel(const float* __restrict__ delta,
                                   const float* __restrict__ u,
                                   const float* __restrict__ xdbl,
                                   const float* __restrict__ A_log,
                                   const float* __restrict__ R,
                                   float* __restrict__ yacc)
{
    int gI = blockIdx.x * blockDim.x + threadIdx.x;   // 0..32767
    int d = gI >> 4;
    int n = gI & 15;
    float An = -fast_exp(A_log[gI]);
    const float* Rd = R + (size_t)d * LSEQ;

    float thresh = 90.0f / (-An);
    int lo = 0, hi = LSEQ;
    while (lo < hi) {
        int mid = (lo + hi) >> 1;
        if (Rd[mid] < thresh) hi = mid; else lo = mid + 1;
    }

    float c = 0.0f;
    for (int t = lo; t < LSEQ; t++) {
        float w  = fast_exp(An * Rd[t]);
        float de = delta[(size_t)t * DIN + d];
        float uu = u[(size_t)t * DIN + d];
        float Bn = xdbl[(size_t)t * XD + DTR + n];
        float Cn = xdbl[(size_t)t * XD + DTR + NST + n];
        c = fmaf(de * uu * Bn, w, c);
        float xs = c * fast_rcp(w + 1e-12f);
        atomicAdd(&yacc[(size_t)t * DIN + d], xs * Cn);
    }
}

// ---------------- finalize: y = (yacc + u*D) * swish(res) ----------------
__global__ void finalize_y_kernel(const float* __restrict__ yacc,
                                  const float* __restrict__ u,
                                  const float* __restrict__ xr,
                                  const float* __restrict__ Dv,
                                  float* __restrict__ y)
{
    int idx = blockIdx.x * blockDim.x + threadIdx.x;
    if (idx >= LSEQ * DIN) return;
    int t = idx >> 11;
    int d = idx & (DIN - 1);
    float res = xr[(size_t)t * (2 * DIN) + DIN + d];
    y[idx] = (yacc[idx] + u[idx] * Dv[d]) * swish_f(res);
}

// ---------------- launch ----------------
extern "C" void kernel_launch(void* const* d_in, const int* in_sizes, int n_in,
                              void* d_out, int out_size)
{
    const float* x      = (const float*)d_in[0];
    const float* W_in   = (const float*)d_in[1];
    const float* conv_w = (const float*)d_in[2];
    const float* conv_b = (const float*)d_in[3];
    const float* W_x    = (const float*)d_in[4];
    const float* W_dt   = (const float*)d_in[5];
    const float* b_dt   = (const float*)d_in[6];
    const float* A_log  = (const float*)d_in[7];
    const float* Dv     = (const float*)d_in[8];
    const float* W_out  = (const float*)d_in[9];
    const float* b_out  = (const float*)d_in[10];
    float* out = (float*)d_out;
    (void)in_sizes; (void)n_in; (void)out_size;

    float *xr, *xi, *xdbl, *delta, *Rbuf, *yacc, *y, *part;
    cudaGetSymbolAddress((void**)&xr,    g_xr);
    cudaGetSymbolAddress((void**)&xi,    g_xi);
    cudaGetSymbolAddress((void**)&xdbl,  g_xdbl);
    cudaGetSymbolAddress((void**)&delta, g_delta);
    cudaGetSymbolAddress((void**)&Rbuf,  g_R);
    cudaGetSymbolAddress((void**)&yacc,  g_yacc);
    cudaGetSymbolAddress((void**)&y,     g_y);
    cudaGetSymbolAddress((void**)&part,  g_part);

    const int SMEM3 = 2 * 2 * (128 * 36 + 32 * 132) * 4;   // 141312 B (3xTF32 stages)
    const int SMEM1 = 2 * (128 * 36 + 32 * 132) * 4;       // 70656 B
    cudaFuncSetAttribute(gemm_tf32_kernel<true, 0>,
                         cudaFuncAttributeMaxDynamicSharedMemorySize, SMEM3);
    cudaFuncSetAttribute(gemm_tf32_kernel<false, 1>,
                         cudaFuncAttributeMaxDynamicSharedMemorySize, SMEM1);

    dim3 blk(256);

    // 1) x_and_res = x @ W_in   (2048 x 4096 x 1024) — 3xTF32 tensor cores
    gemm_tf32_kernel<true, 0><<<dim3((2 * DIN) / 128, LSEQ / 128), blk, SMEM3>>>(
        x, W_in, nullptr, xr, LSEQ, 2 * DIN, DM);

    // 2) xi = swish(causal depthwise conv(xi_raw) + conv_b)
    conv_swish_kernel<<<(LSEQ * DIN + 255) / 256, blk>>>(xr, conv_w, conv_b, xi);

    // 3) x_dbl = xi @ W_x       (2048 x 96 x 2048), split-K=16 fp32
    gemm_kernel<<<dim3(1, LSEQ / BM, 16), blk>>>(
        xi, W_x, nullptr, part, LSEQ, XD, DIN, DIN, 0);
    reduce_split_kernel<<<(LSEQ * XD + 255) / 256, blk>>>(part, xdbl, LSEQ * XD, 16);

    // 4) delta = softplus(delta_r @ W_dt + b_dt)  (2048 x 2048 x 64) fp32
    gemm_kernel<<<dim3(DIN / BN, LSEQ / BM, 1), blk>>>(
        xdbl, W_dt, b_dt, delta, LSEQ, DIN, DTR, XD, 2);

    // 5) selective scan: suffix sums + sparse live-tail walk
    zero_kernel<<<(LSEQ * DIN + 255) / 256, blk>>>(yacc, LSEQ * DIN);
    suffix_scan_kernel<<<DIN, blk>>>(delta, Rbuf);
    scan_sparse_kernel<<<(DIN * NST) / 256, blk>>>(delta, xi, xdbl, A_log, Rbuf, yacc);
    finalize_y_kernel<<<(LSEQ * DIN + 255) / 256, blk>>>(yacc, xi, xr, Dv, y);

    // 6) out = y_gated @ W_out + b_out  (2048 x 1024 x 2048) — TF32 tensor cores
    gemm_tf32_kernel<false, 1><<<dim3(DM / 128, LSEQ / 128), blk, SMEM1>>>(
        y, W_out, b_out, out, LSEQ, DM, DIN);
}

// round 4
// speedup vs baseline: 7.7569x; 1.2645x over previous
#include <cuda_runtime.h>
#include <cstddef>
#include <cstdint>

#define LSEQ 2048
#define DM   1024
#define DIN  2048
#define NST  16
#define DTR  64
#define XD   96     // DTR + 2*NST
#define KCONV 4

// ---------------- scratch (device globals; no allocation allowed) ----------------
__device__ float g_xr[(size_t)LSEQ * 2 * DIN];            // [xi_raw | res]
__device__ float g_xi[(size_t)LSEQ * DIN];                // conv+swish output (u)
__device__ float g_xdbl[(size_t)LSEQ * XD];               // delta_r | B | C
__device__ float g_delta[(size_t)LSEQ * DIN];
__device__ float g_R[(size_t)DIN * LSEQ];                 // suffix sums of delta, [d][t]
__device__ float g_yacc[(size_t)LSEQ * DIN];
__device__ float g_y[(size_t)LSEQ * DIN];
__device__ float g_part[(size_t)16 * LSEQ * XD];          // split-K partials for GEMM2

// ---------------- helpers ----------------
__device__ __forceinline__ float fast_exp(float x) {
    float y;
    asm("ex2.approx.f32 %0, %1;" : "=f"(y) : "f"(x * 1.4426950408889634f));
    return y;
}
__device__ __forceinline__ float fast_rcp(float x) {
    float y;
    asm("rcp.approx.f32 %0, %1;" : "=f"(y) : "f"(x));
    return y;
}
__device__ __forceinline__ float swish_f(float v) {
    return v / (1.0f + fast_exp(-v));
}
__device__ __forceinline__ float softplus_f(float v) {
    return log1pf(fast_exp(-fabsf(v))) + fmaxf(v, 0.0f);
}
__device__ __forceinline__ float tf32_rna(float x) {
    uint32_t u;
    asm("cvt.rna.tf32.f32 %0, %1;" : "=r"(u) : "f"(x));
    return __uint_as_float(u);
}
__device__ __forceinline__ void mma8(float* d, const uint32_t* a, const uint32_t* b) {
    asm volatile("mma.sync.aligned.m16n8k8.row.col.f32.tf32.tf32.f32 "
        "{%0,%1,%2,%3}, {%4,%5,%6,%7}, {%8,%9}, {%0,%1,%2,%3};"
        : "+f"(d[0]), "+f"(d[1]), "+f"(d[2]), "+f"(d[3])
        : "r"(a[0]), "r"(a[1]), "r"(a[2]), "r"(a[3]), "r"(b[0]), "r"(b[1]));
}

// =============== TF32 tensor-core GEMM: C[M,N] = A[M,K]@B[K,N] (+bias) =========
// 128x128x32 tile, 256 threads (8 warps as 2x4 over 64x32 warp tiles).
// THREE=true: 3xTF32 (hi/lo split, ~fp32 accuracy).
// MODE: 0 none, 1 +bias, 2 +bias then softplus.
// A row stride = lda (>=K), B row stride = ldb, C row stride = ldc. M,N,K mult of 128/128/32.
template<bool THREE, int MODE>
__global__ void __launch_bounds__(256)
gemm_tf32_kernel(const float* __restrict__ A, const float* __restrict__ B,
                 const float* __restrict__ bias, float* __restrict__ C,
                 int M, int N, int K, int lda, int ldb, int ldc)
{
    extern __shared__ float sm[];
    constexpr int AST = 36;             // A tile row stride (conflict-free: g*4+tg bijective)
    constexpr int BST = 136;            // B tile row stride (conflict-free: tg*8+g bijective)
    constexpr int ASZ = 128 * AST;
    constexpr int BSZ = 32 * BST;
    constexpr int STAGE = THREE ? 2 * (ASZ + BSZ) : (ASZ + BSZ);

    const int tid  = threadIdx.x;
    const int wid  = tid >> 5;
    const int lane = tid & 31;
    const int g    = lane >> 2;
    const int tg   = lane & 3;
    const int wm0  = (wid >> 2) << 6;
    const int wn0  = (wid & 3) << 5;
    const int m0   = blockIdx.y << 7;
    const int n0   = blockIdx.x << 7;

    float acc[4][4][4];
#pragma unroll
    for (int i = 0; i < 4; i++)
#pragma unroll
        for (int j = 0; j < 4; j++)
#pragma unroll
            for (int q = 0; q < 4; q++) acc[i][j][q] = 0.0f;

    float4 ra[4], rb[4];

    auto ldg_tile = [&](int k0) {
#pragma unroll
        for (int i = 0; i < 4; i++) {
            int lin = tid + (i << 8);
            ra[i] = *(const float4*)(A + (size_t)(m0 + (lin >> 3)) * lda + k0 + ((lin & 7) << 2));
            rb[i] = *(const float4*)(B + (size_t)(k0 + (lin >> 5)) * ldb + n0 + ((lin & 31) << 2));
        }
    };

    auto sts_tile = [&](int s) {
        float* As_h = sm + s * STAGE;
        float* Bs_h = As_h + (THREE ? 2 * ASZ : ASZ);
#pragma unroll
        for (int i = 0; i < 4; i++) {
            int lin = tid + (i << 8);
            int arow = lin >> 3, acol = (lin & 7) << 2;
            float4 h;
            h.x = tf32_rna(ra[i].x); h.y = tf32_rna(ra[i].y);
            h.z = tf32_rna(ra[i].z); h.w = tf32_rna(ra[i].w);
            *(float4*)(As_h + arow * AST + acol) = h;
            if (THREE) {
                float4 l;
                l.x = tf32_rna(ra[i].x - h.x); l.y = tf32_rna(ra[i].y - h.y);
                l.z = tf32_rna(ra[i].z - h.z); l.w = tf32_rna(ra[i].w - h.w);
                *(float4*)(As_h + ASZ + arow * AST + acol) = l;
            }
            int brow = lin >> 5, bcol = (lin & 31) << 2;
            float4 bh;
            bh.x = tf32_rna(rb[i].x); bh.y = tf32_rna(rb[i].y);
            bh.z = tf32_rna(rb[i].z); bh.w = tf32_rna(rb[i].w);
            *(float4*)(Bs_h + brow * BST + bcol) = bh;
            if (THREE) {
                float4 bl;
                bl.x = tf32_rna(rb[i].x - bh.x); bl.y = tf32_rna(rb[i].y - bh.y);
                bl.z = tf32_rna(rb[i].z - bh.z); bl.w = tf32_rna(rb[i].w - bh.w);
                *(float4*)(Bs_h + BSZ + brow * BST + bcol) = bl;
            }
        }
    };

    auto compute = [&](int s) {
        const float* As_h = sm + s * STAGE;
        const float* As_l = As_h + ASZ;
        const float* Bs_h = As_h + (THREE ? 2 * ASZ : ASZ);
        const float* Bs_l = Bs_h + BSZ;
#pragma unroll
        for (int j = 0; j < 4; j++) {
            const int kk = j << 3;
            uint32_t ah[4][4], bh[4][2];
            uint32_t al[4][4], bl[4][2];
#pragma unroll
            for (int nf = 0; nf < 4; nf++) {
                int bn = wn0 + (nf << 3) + g;
                bh[nf][0] = __float_as_uint(Bs_h[(kk + tg) * BST + bn]);
                bh[nf][1] = __float_as_uint(Bs_h[(kk + tg + 4) * BST + bn]);
                if (THREE) {
                    bl[nf][0] = __float_as_uint(Bs_l[(kk + tg) * BST + bn]);
                    bl[nf][1] = __float_as_uint(Bs_l[(kk + tg + 4) * BST + bn]);
                }
            }
#pragma unroll
            for (int mf = 0; mf < 4; mf++) {
                int rm = (wm0 + (mf << 4) + g) * AST + kk + tg;
                ah[mf][0] = __float_as_uint(As_h[rm]);
                ah[mf][1] = __float_as_uint(As_h[rm + 8 * AST]);
                ah[mf][2] = __float_as_uint(As_h[rm + 4]);
                ah[mf][3] = __float_as_uint(As_h[rm + 8 * AST + 4]);
                if (THREE) {
                    al[mf][0] = __float_as_uint(As_l[rm]);
                    al[mf][1] = __float_as_uint(As_l[rm + 8 * AST]);
                    al[mf][2] = __float_as_uint(As_l[rm + 4]);
                    al[mf][3] = __float_as_uint(As_l[rm + 8 * AST + 4]);
                }
            }
#pragma unroll
            for (int mf = 0; mf < 4; mf++)
#pragma unroll
                for (int nf = 0; nf < 4; nf++) {
                    mma8(acc[mf][nf], ah[mf], bh[nf]);
                    if (THREE) {
                        mma8(acc[mf][nf], ah[mf], bl[nf]);
                        mma8(acc[mf][nf], al[mf], bh[nf]);
                    }
                }
        }
    };

    const int nt = K >> 5;
    ldg_tile(0);
    sts_tile(0);
    __syncthreads();
    for (int t = 0; t < nt; t++) {
        if (t + 1 < nt) ldg_tile((t + 1) << 5);
        compute(t & 1);
        if (t + 1 < nt) {
            __syncthreads();
            sts_tile((t + 1) & 1);
            __syncthreads();
        }
    }

    // epilogue
#pragma unroll
    for (int mf = 0; mf < 4; mf++)
#pragma unroll
        for (int nf = 0; nf < 4; nf++) {
            int row = m0 + wm0 + (mf << 4) + g;
            int col = n0 + wn0 + (nf << 3) + (tg << 1);
            float b0 = 0.0f, b1 = 0.0f;
            if (MODE >= 1) { b0 = bias[col]; b1 = bias[col + 1]; }
            float v00 = acc[mf][nf][0] + b0, v01 = acc[mf][nf][1] + b1;
            float v10 = acc[mf][nf][2] + b0, v11 = acc[mf][nf][3] + b1;
            if (MODE == 2) {
                v00 = softplus_f(v00); v01 = softplus_f(v01);
                v10 = softplus_f(v10); v11 = softplus_f(v11);
            }
            *(float2*)(C + (size_t)row * ldc + col) = make_float2(v00, v01);
            *(float2*)(C + (size_t)(row + 8) * ldc + col) = make_float2(v10, v11);
        }
}

// ---------------- fp32 SIMT GEMM (kept for skinny GEMM2) ----------------
#define BM 128
#define BN 128
#define BK 16

__global__ void __launch_bounds__(256)
gemm_kernel(const float* __restrict__ A, const float* __restrict__ B,
            const float* __restrict__ bias, float* __restrict__ C,
            int M, int N, int K, int lda, int mode)
{
    __shared__ __align__(16) float As[BK][BM];
    __shared__ __align__(16) float Bs[BK][BN];

    const int tid = threadIdx.x;
    const int tx = tid & 15;
    const int ty = tid >> 4;
    const int m0 = blockIdx.y * BM;
    const int n0 = blockIdx.x * BN;

    const int splits = gridDim.z;
    const int Kc = K / splits;
    const int kbeg = blockIdx.z * Kc;
    const int kend = kbeg + Kc;

    float acc[8][8];
#pragma unroll
    for (int i = 0; i < 8; i++)
#pragma unroll
        for (int j = 0; j < 8; j++) acc[i][j] = 0.0f;

    for (int k0 = kbeg; k0 < kend; k0 += BK) {
#pragma unroll
        for (int i = 0; i < 2; i++) {
            int lin = tid + i * 256;
            int r = lin >> 2;
            int kk = (lin & 3) * 4;
            float4 v = *(const float4*)(A + (size_t)(m0 + r) * lda + (k0 + kk));
            As[kk + 0][r] = v.x; As[kk + 1][r] = v.y;
            As[kk + 2][r] = v.z; As[kk + 3][r] = v.w;
        }
#pragma unroll
        for (int i = 0; i < 2; i++) {
            int lin = tid + i * 256;
            int r = lin >> 5;
            int c = (lin & 31) * 4;
            int gn = n0 + c;
            float4 v = make_float4(0.f, 0.f, 0.f, 0.f);
            if (gn < N) v = *(const float4*)(B + (size_t)(k0 + r) * N + gn);
            *(float4*)&Bs[r][c] = v;
        }
        __syncthreads();

#pragma unroll
        for (int k = 0; k < BK; k++) {
            float rva[8], rvb[8];
            *(float4*)&rva[0] = *(const float4*)&As[k][ty * 8];
            *(float4*)&rva[4] = *(const float4*)&As[k][ty * 8 + 4];
            *(float4*)&rvb[0] = *(const float4*)&Bs[k][tx * 8];
            *(float4*)&rvb[4] = *(const float4*)&Bs[k][tx * 8 + 4];
#pragma unroll
            for (int i = 0; i < 8; i++)
#pragma unroll
                for (int j = 0; j < 8; j++)
                    acc[i][j] = fmaf(rva[i], rvb[j], acc[i][j]);
        }
        __syncthreads();
    }

    float* Cout = C;
    if (splits > 1) Cout += (size_t)blockIdx.z * M * N;

#pragma unroll
    for (int i = 0; i < 8; i++) {
        int gm = m0 + ty * 8 + i;
        if (gm >= M) continue;
#pragma unroll
        for (int j = 0; j < 8; j++) {
            int gn = n0 + tx * 8 + j;
            if (gn >= N) continue;
            float v = acc[i][j];
            if (splits == 1) {
                if (mode >= 1 && bias) v += bias[gn];
                if (mode == 2) v = softplus_f(v);
            }
            Cout[(size_t)gm * N + gn] = v;
        }
    }
}

__global__ void reduce_split_kernel(const float* __restrict__ part, float* __restrict__ out,
                                    int total, int splits)
{
    int i = blockIdx.x * blockDim.x + threadIdx.x;
    if (i >= total) return;
    float s = 0.0f;
    for (int z = 0; z < splits; z++) s += part[(size_t)z * total + i];
    out[i] = s;
}

// ---------------- depthwise causal conv (K=4) + bias + swish -------------------
// 4 outputs (consecutive t) per thread: 7 loads / 4 outputs.
__global__ void conv_swish_kernel(const float* __restrict__ xr,
                                  const float* __restrict__ cw,
                                  const float* __restrict__ cb,
                                  float* __restrict__ xi)
{
    int idx = blockIdx.x * blockDim.x + threadIdx.x;    // over (LSEQ/4)*DIN
    if (idx >= (LSEQ / 4) * DIN) return;
    int tb = (idx >> 11) << 2;          // t base (multiple of 4)
    int d  = idx & (DIN - 1);
    float w0 = cw[d * KCONV + 0], w1 = cw[d * KCONV + 1];
    float w2 = cw[d * KCONV + 2], w3 = cw[d * KCONV + 3];
    float bias = cb[d];
    float v[7];
#pragma unroll
    for (int k = 0; k < 7; k++) {
        int tt = tb - 3 + k;
        v[k] = (tt >= 0) ? xr[(size_t)tt * (2 * DIN) + d] : 0.0f;
    }
#pragma unroll
    for (int o = 0; o < 4; o++) {
        float acc = bias;
        acc = fmaf(w0, v[o], acc);
        acc = fmaf(w1, v[o + 1], acc);
        acc = fmaf(w2, v[o + 2], acc);
        acc = fmaf(w3, v[o + 3], acc);
        xi[(size_t)(tb + o) * DIN + d] = swish_f(acc);
    }
}

// ---------------- suffix scan (+ fused yacc zeroing) ---------------------------
__global__ void suffix_scan_kernel(const float* __restrict__ delta, float* __restrict__ R,
                                   float* __restrict__ yacc)
{
    __shared__ float sh[256];
    const int d = blockIdx.x;
    const int tid = threadIdx.x;

    // fused: zero yacc (each block clears its 1/DIN slice; 4 float4s per thread)
    {
        float4* p = (float4*)(yacc + (size_t)d * (LSEQ * DIN / DIN));
        // note: LSEQ*DIN/DIN = LSEQ*... we clear by global slice instead:
    }
    {
        const int per_blk = (LSEQ * DIN) / (DIN);      // 2048 floats per block
        float4* base = (float4*)(yacc + (size_t)blockIdx.x * per_blk);
#pragma unroll
        for (int i = 0; i < per_blk / 4 / 256 + ((per_blk / 4) % 256 ? 1 : 0); i++) {
            int j = tid + i * 256;
            if (j < per_blk / 4) base[j] = make_float4(0.f, 0.f, 0.f, 0.f);
        }
    }

    const int r = 255 - tid;
    float carry = 0.0f;
    for (int c = LSEQ / 256 - 1; c >= 0; c--) {
        int t = c * 256 + tid;
        float v = delta[(size_t)t * DIN + d];
        sh[r] = v;
        __syncthreads();
        float val = v;
#pragma unroll
        for (int off = 1; off < 256; off <<= 1) {
            float add = (r >= off) ? sh[r - off] : 0.0f;
            __syncthreads();
            val += add;
            sh[r] = val;
            __syncthreads();
        }
        R[(size_t)d * LSEQ + t] = (val - v) + carry;
        float chunk_total = sh[255];
        __syncthreads();
        carry += chunk_total;
    }
}

// ---------------- sparse scan forward (live-tail only) -------------------------
__global__ void scan_sparse_kernel(const float* __restrict__ delta,
                                   const float* __restrict__ u,
                                   const float* __restrict__ xdbl,
                                   const float* __restrict__ A_log,
                                   const float* __restrict__ R,
                                   float* __restrict__ yacc)
{
    int gI = blockIdx.x * blockDim.x + threadIdx.x;
    int d = gI >> 4;
    int n = gI & 15;
    float An = -fast_exp(A_log[gI]);
    const float* Rd = R + (size_t)d * LSEQ;

    float thresh = 90.0f / (-An);
    int lo = 0, hi = LSEQ;
    while (lo < hi) {
        int mid = (lo + hi) >> 1;
        if (Rd[mid] < thresh) hi = mid; else lo = mid + 1;
    }

    float c = 0.0f;
    for (int t = lo; t < LSEQ; t++) {
        float w  = fast_exp(An * Rd[t]);
        float de = delta[(size_t)t * DIN + d];
        float uu = u[(size_t)t * DIN + d];
        float Bn = xdbl[(size_t)t * XD + DTR + n];
        float Cn = xdbl[(size_t)t * XD + DTR + NST + n];
        c = fmaf(de * uu * Bn, w, c);
        float xs = c * fast_rcp(w + 1e-12f);
        atomicAdd(&yacc[(size_t)t * DIN + d], xs * Cn);
    }
}

// ---------------- finalize: y = (yacc + u*D) * swish(res) ----------------------
__global__ void finalize_y_kernel(const float* __restrict__ yacc,
                                  const float* __restrict__ u,
                                  const float* __restrict__ xr,
                                  const float* __restrict__ Dv,
                                  float* __restrict__ y)
{
    int idx = blockIdx.x * blockDim.x + threadIdx.x;
    if (idx >= LSEQ * DIN) return;
    int t = idx >> 11;
    int d = idx & (DIN - 1);
    float res = xr[(size_t)t * (2 * DIN) + DIN + d];
    y[idx] = (yacc[idx] + u[idx] * Dv[d]) * swish_f(res);
}

// ---------------- launch ----------------
extern "C" void kernel_launch(void* const* d_in, const int* in_sizes, int n_in,
                              void* d_out, int out_size)
{
    const float* x      = (const float*)d_in[0];
    const float* W_in   = (const float*)d_in[1];
    const float* conv_w = (const float*)d_in[2];
    const float* conv_b = (const float*)d_in[3];
    const float* W_x    = (const float*)d_in[4];
    const float* W_dt   = (const float*)d_in[5];
    const float* b_dt   = (const float*)d_in[6];
    const float* A_log  = (const float*)d_in[7];
    const float* Dv     = (const float*)d_in[8];
    const float* W_out  = (const float*)d_in[9];
    const float* b_out  = (const float*)d_in[10];
    float* out = (float*)d_out;
    (void)in_sizes; (void)n_in; (void)out_size;

    float *xr, *xi, *xdbl, *delta, *Rbuf, *yacc, *y, *part;
    cudaGetSymbolAddress((void**)&xr,    g_xr);
    cudaGetSymbolAddress((void**)&xi,    g_xi);
    cudaGetSymbolAddress((void**)&xdbl,  g_xdbl);
    cudaGetSymbolAddress((void**)&delta, g_delta);
    cudaGetSymbolAddress((void**)&Rbuf,  g_R);
    cudaGetSymbolAddress((void**)&yacc,  g_yacc);
    cudaGetSymbolAddress((void**)&y,     g_y);
    cudaGetSymbolAddress((void**)&part,  g_part);

    constexpr int ASZ = 128 * 36, BSZ = 32 * 136;
    const int SMEM3 = 2 * 2 * (ASZ + BSZ) * 4;   // 143360 B
    const int SMEM1 = 2 * (ASZ + BSZ) * 4;       // 71680 B
    cudaFuncSetAttribute(gemm_tf32_kernel<true, 0>,
                         cudaFuncAttributeMaxDynamicSharedMemorySize, SMEM3);
    cudaFuncSetAttribute(gemm_tf32_kernel<true, 2>,
                         cudaFuncAttributeMaxDynamicSharedMemorySize, SMEM3);
    cudaFuncSetAttribute(gemm_tf32_kernel<false, 0>,
                         cudaFuncAttributeMaxDynamicSharedMemorySize, SMEM1);
    cudaFuncSetAttribute(gemm_tf32_kernel<false, 1>,
                         cudaFuncAttributeMaxDynamicSharedMemorySize, SMEM1);

    dim3 blk(256);

    // 1a) xi_raw = x @ W_in[:, :DIN]   — 3xTF32 (feeds the exponent-sensitive chain)
    gemm_tf32_kernel<true, 0><<<dim3(DIN / 128, LSEQ / 128), blk, SMEM3>>>(
        x, W_in, nullptr, xr, LSEQ, DIN, DM, DM, 2 * DIN, 2 * DIN);
    // 1b) res = x @ W_in[:, DIN:]      — plain TF32 (only gates the output)
    gemm_tf32_kernel<false, 0><<<dim3(DIN / 128, LSEQ / 128), blk, SMEM1>>>(
        x, W_in + DIN, nullptr, xr + DIN, LSEQ, DIN, DM, DM, 2 * DIN, 2 * DIN);

    // 2) xi = swish(causal depthwise conv(xi_raw) + conv_b)
    conv_swish_kernel<<<((LSEQ / 4) * DIN + 255) / 256, blk>>>(xr, conv_w, conv_b, xi);

    // 3) x_dbl = xi @ W_x  (2048 x 96 x 2048), split-K=16 fp32
    gemm_kernel<<<dim3(1, LSEQ / BM, 16), blk>>>(
        xi, W_x, nullptr, part, LSEQ, XD, DIN, DIN, 0);
    reduce_split_kernel<<<(LSEQ * XD + 255) / 256, blk>>>(part, xdbl, LSEQ * XD, 16);

    // 4) delta = softplus(delta_r @ W_dt + b_dt)  (2048 x 2048 x 64) — 3xTF32 + fused epi
    gemm_tf32_kernel<true, 2><<<dim3(DIN / 128, LSEQ / 128), blk, SMEM3>>>(
        xdbl, W_dt, b_dt, delta, LSEQ, DIN, DTR, XD, DIN, DIN);

    // 5) selective scan: suffix sums (+fused yacc zero) + sparse live-tail walk
    suffix_scan_kernel<<<DIN, blk>>>(delta, Rbuf, yacc);
    scan_sparse_kernel<<<(DIN * NST) / 256, blk>>>(delta, xi, xdbl, A_log, Rbuf, yacc);
    finalize_y_kernel<<<(LSEQ * DIN + 255) / 256, blk>>>(yacc, xi, xr, Dv, y);

    // 6) out = y_gated @ W_out + b_out  (2048 x 1024 x 2048) — TF32
    gemm_tf32_kernel<false, 1><<<dim3(DM / 128, LSEQ / 128), blk, SMEM1>>>(
        y, W_out, b_out, out, LSEQ, DM, DIN, DIN, DM, DM);
}